// round 15
// baseline (speedup 1.0000x reference)
#include <cuda_runtime.h>

#define Bn   32
#define Ln   200
#define Vn   128
#define Gn   384
#define NCn  256
#define NDn  32
#define BTn  (Bn*Ln)          // 6400
#define ASZ  (Bn*Ln*NDn)      // 204800 floats (alpha)
#define HSZ  (Bn*Ln*Vn)       // 819200 floats (h_seq)

// packed-f32x2 helpers (exact fp32 math; halves instruction count)
#define FMA2(acc, a, b) \
    asm("fma.rn.f32x2 %0, %1, %2, %0;" : "+l"(acc) : "l"(a), "l"(b))
#define PACKB(dst, fval) \
    asm("mov.b64 %0, {%1, %1};" : "=l"(dst) : "r"(__float_as_uint(fval)))
__device__ __forceinline__ float2 unpack2(unsigned long long v) {
    unsigned int lo, hi;
    asm("mov.b64 {%0, %1}, %2;" : "=r"(lo), "=r"(hi) : "l"(v));
    return make_float2(__uint_as_float(lo), __uint_as_float(hi));
}

// scratch (module-load allocated, not runtime alloc)
__device__ float g_gx[(size_t)BTn*Gn];     // [bt][384] GRU input projections
__device__ float g_p [(size_t)BTn*Vn];     // [bt][128] memory-path projections
__device__ float g_rows[(size_t)BTn*NDn];  // [bt][32] memory row written at t
__device__ int   g_nextA[BTn];             // next t' with same c (else Ln)
__device__ int   g_firstA[Bn*NCn];         // first t with c (else Ln)
__device__ int   g_done[Bn];               // per-batch beta-chain done flags

// ============================================================================
// Kernel A: embed gather + fused GEMM  (M=6400, K=256, N=512)  [R5 verbatim]
// ============================================================================
#define A_PAD  68
#define A_WPAD 132
#define A_SMEM ((256*A_PAD + 2*32*A_WPAD)*4)

__global__ void __launch_bounds__(256, 2) kA(
    const int* __restrict__ c_seq, const int* __restrict__ d_seq,
    const float* __restrict__ r_seq, const float* __restrict__ X,
    const float* __restrict__ v_r,
    const float* __restrict__ W_ih, const float* __restrict__ b_ih,
    const float* __restrict__ W2a,  const float* __restrict__ b2a)
{
    extern __shared__ float sm[];
    float* inT = sm;                      // [k 256][m 68-pad] transposed input
    float* Wt0 = sm + 256*A_PAD;          // two [k 32][n 132-pad] buffers
    const int tid  = threadIdx.x;
    const int lane = tid & 31;
    const int warp = tid >> 5;
    const int bt0  = blockIdx.x * 64;
    const int n0   = blockIdx.y * 128;

    // zero the per-batch done flags (stream order guards kM)
    if (blockIdx.x == 0 && blockIdx.y == 0 && tid < Bn) g_done[tid] = 0;

    // ---- load input tile (gather embedding + r*v_r), transposed ----
    {
        const int m = tid & 63;
        const int q = tid >> 6;          // 0..3
        const int bt = bt0 + m;
        const int c  = c_seq[bt];
        const int d  = d_seq[bt];
        const float r = r_seq[bt];
        if (q < 2) {
            const float4* src = (const float4*)(X + (size_t)(c + NCn*d)*Vn + q*64);
            #pragma unroll
            for (int u = 0; u < 16; u++) {
                float4 v = src[u];
                int k = q*64 + u*4;
                inT[(k+0)*A_PAD+m] = v.x; inT[(k+1)*A_PAD+m] = v.y;
                inT[(k+2)*A_PAD+m] = v.z; inT[(k+3)*A_PAD+m] = v.w;
            }
        } else {
            const int kb = (q - 2) * 64;
            const float4* src = (const float4*)(v_r + kb);
            #pragma unroll
            for (int u = 0; u < 16; u++) {
                float4 v = src[u];
                int k = 128 + kb + u*4;
                inT[(k+0)*A_PAD+m] = r*v.x; inT[(k+1)*A_PAD+m] = r*v.y;
                inT[(k+2)*A_PAD+m] = r*v.z; inT[(k+3)*A_PAD+m] = r*v.w;
            }
        }
    }

    const int nl  = tid & 127;
    const int kq2 = tid >> 7;             // 0..1
    const int n   = n0 + nl;
    const float4* wsrc = (const float4*)((n < Gn)
                       ? (W_ih + (size_t)n*256)
                       : (W2a + (size_t)(n - Gn)*384 + 128));

    float4 wr0 = wsrc[kq2*4+0], wr1 = wsrc[kq2*4+1],
           wr2 = wsrc[kq2*4+2], wr3 = wsrc[kq2*4+3];

    const int mq = warp * 8;              // 0..56
    const int nq = lane * 4;              // 0..124

    unsigned long long acc[16];
    #pragma unroll
    for (int i = 0; i < 16; i++) acc[i] = 0ull;

    for (int kb = 0; kb < 8; kb++) {
        float* Wt = Wt0 + (kb & 1) * (32*A_WPAD);
        {
            int k = kq2*16;
            Wt[(k+ 0)*A_WPAD+nl]=wr0.x; Wt[(k+ 1)*A_WPAD+nl]=wr0.y; Wt[(k+ 2)*A_WPAD+nl]=wr0.z; Wt[(k+ 3)*A_WPAD+nl]=wr0.w;
            Wt[(k+ 4)*A_WPAD+nl]=wr1.x; Wt[(k+ 5)*A_WPAD+nl]=wr1.y; Wt[(k+ 6)*A_WPAD+nl]=wr1.z; Wt[(k+ 7)*A_WPAD+nl]=wr1.w;
            Wt[(k+ 8)*A_WPAD+nl]=wr2.x; Wt[(k+ 9)*A_WPAD+nl]=wr2.y; Wt[(k+10)*A_WPAD+nl]=wr2.z; Wt[(k+11)*A_WPAD+nl]=wr2.w;
            Wt[(k+12)*A_WPAD+nl]=wr3.x; Wt[(k+13)*A_WPAD+nl]=wr3.y; Wt[(k+14)*A_WPAD+nl]=wr3.z; Wt[(k+15)*A_WPAD+nl]=wr3.w;
        }
        if (kb < 7) {
            wr0 = wsrc[(kb+1)*8 + kq2*4 + 0];
            wr1 = wsrc[(kb+1)*8 + kq2*4 + 1];
            wr2 = wsrc[(kb+1)*8 + kq2*4 + 2];
            wr3 = wsrc[(kb+1)*8 + kq2*4 + 3];
        }
        __syncthreads();
        const float* inb = inT + (kb*32)*A_PAD + mq;
        const float* wb  = Wt + nq;
        #pragma unroll
        for (int kk = 0; kk < 32; kk++) {
            float4 aA = *(const float4*)(inb + kk*A_PAD);
            float4 aB = *(const float4*)(inb + kk*A_PAD + 4);
            ulonglong2 wv = *(const ulonglong2*)(wb + kk*A_WPAD);
            unsigned long long p;
            PACKB(p, aA.x); FMA2(acc[ 0], p, wv.x); FMA2(acc[ 1], p, wv.y);
            PACKB(p, aA.y); FMA2(acc[ 2], p, wv.x); FMA2(acc[ 3], p, wv.y);
            PACKB(p, aA.z); FMA2(acc[ 4], p, wv.x); FMA2(acc[ 5], p, wv.y);
            PACKB(p, aA.w); FMA2(acc[ 6], p, wv.x); FMA2(acc[ 7], p, wv.y);
            PACKB(p, aB.x); FMA2(acc[ 8], p, wv.x); FMA2(acc[ 9], p, wv.y);
            PACKB(p, aB.y); FMA2(acc[10], p, wv.x); FMA2(acc[11], p, wv.y);
            PACKB(p, aB.z); FMA2(acc[12], p, wv.x); FMA2(acc[13], p, wv.y);
            PACKB(p, aB.w); FMA2(acc[14], p, wv.x); FMA2(acc[15], p, wv.y);
        }
    }

    const int nn = n0 + nq;
    if (n0 < Gn) {
        float b0=b_ih[nn], b1=b_ih[nn+1], b2=b_ih[nn+2], b3=b_ih[nn+3];
        #pragma unroll
        for (int i = 0; i < 8; i++) {
            float2 lo = unpack2(acc[2*i]), hi = unpack2(acc[2*i+1]);
            *(float4*)(g_gx + (size_t)(bt0+mq+i)*Gn + nn) =
                make_float4(lo.x+b0, lo.y+b1, hi.x+b2, hi.y+b3);
        }
    } else {
        const int pc = nn - Gn;
        float b0=b2a[pc], b1=b2a[pc+1], b2=b2a[pc+2], b3=b2a[pc+3];
        #pragma unroll
        for (int i = 0; i < 8; i++) {
            float2 lo = unpack2(acc[2*i]), hi = unpack2(acc[2*i+1]);
            *(float4*)(g_p + (size_t)(bt0+mq+i)*Vn + pc) =
                make_float4(lo.x+b0, lo.y+b1, hi.x+b2, hi.y+b3);
        }
    }
}

// ============================================================================
// Kernel M: grid 144 blocks x 384 threads (one wave).
//   blocks 0..31  : beta chain (R5 verbatim) + index epilogue.
//   blocks 32..47 : GRU scan, TWO batches per block (shared W_hh registers;
//                   one barrier pair per double-step; phase B on 256 threads).
//   blocks 48..143: interval fill of C_seq (3 blocks per batch).
// ============================================================================
__global__ void __launch_bounds__(384, 1) kM(
    const int* __restrict__ c_seq, const int* __restrict__ d_seq,
    const float* __restrict__ W_hh, const float* __restrict__ b_hh,
    const float* __restrict__ v_beta, const float* __restrict__ W2a,
    const float* __restrict__ W2b, const float* __restrict__ b2b,
    float* __restrict__ out)
{
    __shared__ __align__(16) char smemu[33792];   // 33 KB union
    const int blk = blockIdx.x;
    const int tid = threadIdx.x;

    if (blk < 32) {
        // ---------------- beta chain (per batch) ----------------
        float* C_sh   = (float*)smemu;            // 8192 floats (32 KB)
        float* u_sh   = C_sh + NCn*NDn;           // 128
        float* pre_sh = u_sh + 128;               // 128 (16B aligned)
        const int b = blk;

        for (int i = tid; i < NCn*NDn; i += 384) C_sh[i] = 0.f;
        if (tid < 128) {
            float acc = 0.f;
            const float* wr = W2a + (size_t)tid*384;
            #pragma unroll 8
            for (int j = 0; j < 128; j++) acc += v_beta[j]*wr[j];
            u_sh[tid] = acc;
        }

        float4 wb0={0,0,0,0}, wb1={0,0,0,0}, wb2={0,0,0,0}, wb3={0,0,0,0};
        float bb = 0.f;
        int dd = 0, s = 0;
        if (tid < 256) {
            dd = tid >> 3; s = tid & 7;
            const float4* wr = (const float4*)(W2b + (size_t)dd*128 + s*16);
            wb0 = wr[0]; wb1 = wr[1]; wb2 = wr[2]; wb3 = wr[3];
            bb = b2b[dd];
        }
        __syncthreads();

        const float* pp = g_p + (size_t)b*Ln*Vn;
        const int* cs = c_seq + b*Ln;
        const int* ds = d_seq + b*Ln;

        int ct = cs[0], dt = ds[0];
        float pv0 = 0.f, pv1 = 0.f;
        if (tid < 128) { pv0 = pp[tid]; pv1 = pp[Vn + tid]; }

        for (int t = 0; t < Ln; t++) {
            float pvN = 0.f;
            if (t+2 < Ln && tid < 128) pvN = pp[(size_t)(t+2)*Vn + tid];
            int ctn = ct, dtn = dt;
            if (t+1 < Ln) { ctn = cs[t+1]; dtn = ds[t+1]; }

            const float beta = C_sh[ct*NDn + dt];
            if (tid < 128) pre_sh[tid] = fmaxf(beta*u_sh[tid] + pv0, 0.f);
            __syncthreads();
            if (tid < 256) {
                const float4* pr = (const float4*)&pre_sh[s*16];
                float4 p0 = pr[0], p1 = pr[1], p2 = pr[2], p3 = pr[3];
                float acc = wb0.x*p0.x + wb0.y*p0.y + wb0.z*p0.z + wb0.w*p0.w
                          + wb1.x*p1.x + wb1.y*p1.y + wb1.z*p1.z + wb1.w*p1.w
                          + wb2.x*p2.x + wb2.y*p2.y + wb2.z*p2.z + wb2.w*p2.w
                          + wb3.x*p3.x + wb3.y*p3.y + wb3.z*p3.z + wb3.w*p3.w;
                acc += __shfl_down_sync(0xffffffffu, acc, 4, 8);
                acc += __shfl_down_sync(0xffffffffu, acc, 2, 8);
                acc += __shfl_down_sync(0xffffffffu, acc, 1, 8);
                if (s == 0) {
                    const float v = acc + bb;
                    C_sh[ct*NDn + dd] = v;
                    g_rows[((size_t)b*Ln + t)*NDn + dd] = v;
                }
            }
            __syncthreads();
            ct = ctn; dt = dtn; pv0 = pv1; pv1 = pvN;
        }

        // ---- index epilogue ----
        __syncthreads();
        int* csm = (int*)smemu;
        for (int i = tid; i < Ln; i += 384) csm[i] = cs[i];
        __syncthreads();
        if (tid < Ln) {
            const int c = csm[tid];
            int nt = Ln;
            for (int tt = tid+1; tt < Ln; tt++) if (csm[tt] == c) { nt = tt; break; }
            g_nextA[b*Ln + tid] = nt;
        } else if (tid < Ln + NCn) {
            const int c = tid - Ln;
            int ft = Ln;
            for (int tt = 0; tt < Ln; tt++) if (csm[tt] == c) { ft = tt; break; }
            g_firstA[b*NCn + c] = ft;
        }
        __threadfence();
        __syncthreads();
        if (tid == 0) atomicExch(&g_done[b], 1);

    } else if (blk < 48) {
        // ------------- GRU scan: TWO batches per block -------------
        float* h_shA  = (float*)smemu;        // 128
        float* h_shB  = h_shA + 128;          // 128
        float* s_shA  = h_shB + 128;          // 384
        float* s_shB  = s_shA + 384;          // 384
        float* xn_shA = s_shB + 384;          // 128
        float* xn_shB = xn_shA + 128;         // 128
        const int b0 = (blk - 32) * 2;
        const int b1 = b0 + 1;
        const int g = tid;

        unsigned long long w[64];             // shared across both batches
        {
            const ulonglong2* wr = (const ulonglong2*)(W_hh + (size_t)g*128);
            #pragma unroll
            for (int i = 0; i < 32; i++) {
                ulonglong2 v = wr[i];
                w[2*i] = v.x; w[2*i+1] = v.y;
            }
        }
        const float bh = b_hh[g];
        if (tid < 128) { h_shA[tid] = 0.f; h_shB[tid] = 0.f; }
        __syncthreads();

        float* houtA = out + ASZ + (size_t)b0*Ln*Vn;
        float* houtB = out + ASZ + (size_t)b1*Ln*Vn;
        const float* gxA = g_gx + (size_t)b0*Ln*Gn;
        const float* gxB = g_gx + (size_t)b1*Ln*Gn;
        float xgA0 = gxA[g], xgA1 = gxA[(size_t)Gn + g];
        float xgB0 = gxB[g], xgB1 = gxB[(size_t)Gn + g];

        for (int t = 0; t < Ln; t++) {
            float xgAN = 0.f, xgBN = 0.f;
            if (t+2 < Ln) {
                xgAN = gxA[(size_t)(t+2)*Gn + g];
                xgBN = gxB[(size_t)(t+2)*Gn + g];
            }

            // matvec for batch A
            unsigned long long a0 = 0ull, a1 = 0ull;
            {
                const ulonglong2* h2 = (const ulonglong2*)h_shA;
                #pragma unroll
                for (int kb = 0; kb < 16; kb++) {
                    ulonglong2 hA = h2[kb*2+0];
                    ulonglong2 hB = h2[kb*2+1];
                    FMA2(a0, w[kb*4+0], hA.x); FMA2(a1, w[kb*4+1], hA.y);
                    FMA2(a0, w[kb*4+2], hB.x); FMA2(a1, w[kb*4+3], hB.y);
                }
            }
            // matvec for batch B
            unsigned long long a2 = 0ull, a3 = 0ull;
            {
                const ulonglong2* h2 = (const ulonglong2*)h_shB;
                #pragma unroll
                for (int kb = 0; kb < 16; kb++) {
                    ulonglong2 hA = h2[kb*2+0];
                    ulonglong2 hB = h2[kb*2+1];
                    FMA2(a2, w[kb*4+0], hA.x); FMA2(a3, w[kb*4+1], hA.y);
                    FMA2(a2, w[kb*4+2], hB.x); FMA2(a3, w[kb*4+3], hB.y);
                }
            }
            float2 f0 = unpack2(a0), f1 = unpack2(a1);
            float2 f2 = unpack2(a2), f3 = unpack2(a3);
            const float ghA = (f0.x + f0.y) + (f1.x + f1.y) + bh;
            const float ghB = (f2.x + f2.y) + (f3.x + f3.y) + bh;
            if (g < 256) {
                s_shA[g] = xgA0 + ghA;
                s_shB[g] = xgB0 + ghB;
            } else {
                s_shA[g] = ghA; xn_shA[g-256] = xgA0;
                s_shB[g] = ghB; xn_shB[g-256] = xgB0;
            }
            xgA0 = xgA1; xgA1 = xgAN;
            xgB0 = xgB1; xgB1 = xgBN;
            __syncthreads();
            if (tid < 256) {
                // tid<128 -> batch A gate j=tid; tid 128..255 -> batch B
                const int j = tid & 127;
                float* s_sh  = (tid < 128) ? s_shA  : s_shB;
                float* xn_sh = (tid < 128) ? xn_shA : xn_shB;
                float* h_sh  = (tid < 128) ? h_shA  : h_shB;
                float* hout  = (tid < 128) ? houtA  : houtB;
                float sr = s_sh[j], sz = s_sh[j+128], sn = s_sh[j+256];
                float r = __fdividef(1.f, 1.f + __expf(-sr));
                float z = __fdividef(1.f, 1.f + __expf(-sz));
                float np = xn_sh[j] + r*sn;
                float e  = __expf(-2.f*np);
                float nn = __fdividef(1.f - e, 1.f + e);
                float h  = h_sh[j];
                h = (1.f - z)*nn + z*h;
                h_sh[j] = h;
                hout[(size_t)t*Vn + j] = h;
            }
            __syncthreads();
        }

    } else {
        // -------------------- interval fill of C_seq --------------------
        const int fb  = blk - 48;         // 0..95
        const int b   = fb / 3;
        const int sub = fb % 3;
        if (tid == 0) {
            while (atomicAdd(&g_done[b], 0) == 0) { __nanosleep(200); }
        }
        __syncthreads();

        const int wid = tid >> 5, lane = tid & 31;
        float* Cout = out + ASZ + HSZ + (size_t)b*Ln*NCn*NDn;
        const int* cs = c_seq + b*Ln;

        for (int task = sub*12 + wid; task < Ln + NCn; task += 36) {
            if (task < Ln) {
                const int t  = task;
                const int c  = cs[t];
                const int te = g_nextA[b*Ln + t];
                const float val = g_rows[((size_t)b*Ln + t)*NDn + lane];
                float* dst = Cout + (size_t)t*(NCn*NDn) + c*NDn + lane;
                for (int tp = t; tp < te; tp++) {
                    __stcs(dst, val);             // evict-first: don't thrash L2
                    dst += NCn*NDn;
                }
            } else {
                const int c  = task - Ln;
                const int te = g_firstA[b*NCn + c];
                float* dst = Cout + c*NDn + lane;
                for (int tp = 0; tp < te; tp++) {
                    __stcs(dst, 0.f);
                    dst += NCn*NDn;
                }
            }
        }
    }
}

// ============================================================================
// Kernel C: alpha = relu(h@W1a^T + b1a)@W1b^T + b1b   (M=6400)
// 100 blocks x 512 threads, m=64 tile per block (single wave).  [R14 verbatim]
// ============================================================================
#define C_SMEM ((128*68 + 128*132 + 128*36 + 64*136)*4)   // 155648 B

__global__ void __launch_bounds__(512, 1) kC(
    const float* __restrict__ W1a, const float* __restrict__ b1a,
    const float* __restrict__ W1b, const float* __restrict__ b1b,
    float* __restrict__ out)
{
    extern __shared__ float sm[];
    float* hT   = sm;                       // [j 128][m 68-pad]
    float* WaT  = hT  + 128*68;             // [j 128][i 132-pad]
    float* WbT  = WaT + 128*132;            // [i 128][dd 36-pad]
    float* hid  = WbT + 128*36;             // [m 64][i 136-pad]
    const int tid = threadIdx.x;
    const int bt0 = blockIdx.x * 64;
    const float* hseq = out + ASZ;

    {
        const int m = tid & 63;
        const int jq = tid >> 6;    // 0..7
        const float4* src = (const float4*)(hseq + (size_t)(bt0+m)*Vn + jq*16);
        #pragma unroll
        for (int u = 0; u < 4; u++) {
            float4 v = src[u];
            int j = jq*16 + u*4;
            hT[(j+0)*68+m]=v.x; hT[(j+1)*68+m]=v.y; hT[(j+2)*68+m]=v.z; hT[(j+3)*68+m]=v.w;
        }
    }
    {
        const int i = tid & 127;
        const int jq = tid >> 7;    // 0..3
        const float4* src = (const float4*)(W1a + (size_t)i*128 + jq*32);
        #pragma unroll
        for (int u = 0; u < 8; u++) {
            float4 v = src[u];
            int j = jq*32 + u*4;
            WaT[(j+0)*132+i]=v.x; WaT[(j+1)*132+i]=v.y; WaT[(j+2)*132+i]=v.z; WaT[(j+3)*132+i]=v.w;
        }
    }
    if (tid < 256) {
        const int dd = tid & 31;
        const int iq = tid >> 5;    // 0..7
        const float4* src = (const float4*)(W1b + (size_t)dd*128 + iq*16);
        #pragma unroll
        for (int u = 0; u < 4; u++) {
            float4 v = src[u];
            int i = iq*16 + u*4;
            WbT[(i+0)*36+dd]=v.x; WbT[(i+1)*36+dd]=v.y; WbT[(i+2)*36+dd]=v.z; WbT[(i+3)*36+dd]=v.w;
        }
    }
    __syncthreads();

    {
        const int mq = (tid >> 5) * 4;      // 0..60
        const int iq = (tid & 31) * 4;      // 0..124
        unsigned long long acc[8];
        #pragma unroll
        for (int i = 0; i < 8; i++) acc[i] = 0ull;
        #pragma unroll 8
        for (int j = 0; j < 128; j++) {
            float4 h4 = *(const float4*)&hT[j*68 + mq];           // broadcast
            ulonglong2 wv = *(const ulonglong2*)&WaT[j*132 + iq];
            unsigned long long p;
            PACKB(p, h4.x); FMA2(acc[0], p, wv.x); FMA2(acc[1], p, wv.y);
            PACKB(p, h4.y); FMA2(acc[2], p, wv.x); FMA2(acc[3], p, wv.y);
            PACKB(p, h4.z); FMA2(acc[4], p, wv.x); FMA2(acc[5], p, wv.y);
            PACKB(p, h4.w); FMA2(acc[6], p, wv.x); FMA2(acc[7], p, wv.y);
        }
        float2 u0 = unpack2(acc[0]), u1 = unpack2(acc[1]);
        float2 u2 = unpack2(acc[2]), u3 = unpack2(acc[3]);
        float2 u4 = unpack2(acc[4]), u5 = unpack2(acc[5]);
        float2 u6 = unpack2(acc[6]), u7 = unpack2(acc[7]);
        float b0=b1a[iq], b1=b1a[iq+1], b2=b1a[iq+2], b3=b1a[iq+3];
        *(float4*)&hid[(mq+0)*136 + iq] = make_float4(fmaxf(u0.x+b0,0.f), fmaxf(u0.y+b1,0.f), fmaxf(u1.x+b2,0.f), fmaxf(u1.y+b3,0.f));
        *(float4*)&hid[(mq+1)*136 + iq] = make_float4(fmaxf(u2.x+b0,0.f), fmaxf(u2.y+b1,0.f), fmaxf(u3.x+b2,0.f), fmaxf(u3.y+b3,0.f));
        *(float4*)&hid[(mq+2)*136 + iq] = make_float4(fmaxf(u4.x+b0,0.f), fmaxf(u4.y+b1,0.f), fmaxf(u5.x+b2,0.f), fmaxf(u5.y+b3,0.f));
        *(float4*)&hid[(mq+3)*136 + iq] = make_float4(fmaxf(u6.x+b0,0.f), fmaxf(u6.y+b1,0.f), fmaxf(u7.x+b2,0.f), fmaxf(u7.y+b3,0.f));
    }
    __syncthreads();

    {
        const int m2 = tid & 63;            // 0..63
        const int d4 = (tid >> 6) * 4;      // 0..28
        float c0=0.f, c1=0.f, c2=0.f, c3=0.f;
        const float* hrow = hid + m2*136;
        #pragma unroll 8
        for (int i4 = 0; i4 < 32; i4++) {
            float4 hq = *(const float4*)(hrow + i4*4);
            float4 wA = *(const float4*)&WbT[(i4*4+0)*36 + d4];
            float4 wB = *(const float4*)&WbT[(i4*4+1)*36 + d4];
            float4 wC = *(const float4*)&WbT[(i4*4+2)*36 + d4];
            float4 wD = *(const float4*)&WbT[(i4*4+3)*36 + d4];
            c0 += hq.x*wA.x + hq.y*wB.x + hq.z*wC.x + hq.w*wD.x;
            c1 += hq.x*wA.y + hq.y*wB.y + hq.z*wC.y + hq.w*wD.y;
            c2 += hq.x*wA.z + hq.y*wB.z + hq.z*wC.z + hq.w*wD.z;
            c3 += hq.x*wA.w + hq.y*wB.w + hq.z*wC.w + hq.w*wD.w;
        }
        float4 ov = make_float4(c0 + b1b[d4], c1 + b1b[d4+1], c2 + b1b[d4+2], c3 + b1b[d4+3]);
        *(float4*)&out[(size_t)(bt0+m2)*NDn + d4] = ov;
    }
}

// ============================================================================
extern "C" void kernel_launch(void* const* d_in, const int* in_sizes, int n_in,
                              void* d_out, int out_size)
{
    const int*   c_seq  = (const int*)  d_in[0];
    const int*   d_seq  = (const int*)  d_in[1];
    const float* r_seq  = (const float*)d_in[2];
    const float* X      = (const float*)d_in[3];
    const float* v_r    = (const float*)d_in[4];
    const float* v_beta = (const float*)d_in[5];
    const float* W_ih   = (const float*)d_in[6];
    const float* W_hh   = (const float*)d_in[7];
    const float* b_ih   = (const float*)d_in[8];
    const float* b_hh   = (const float*)d_in[9];
    const float* W1a    = (const float*)d_in[10];
    const float* b1a    = (const float*)d_in[11];
    const float* W1b    = (const float*)d_in[12];
    const float* b1b    = (const float*)d_in[13];
    const float* W2a    = (const float*)d_in[14];
    const float* b2a    = (const float*)d_in[15];
    const float* W2b    = (const float*)d_in[16];
    const float* b2b    = (const float*)d_in[17];
    float* out = (float*)d_out;

    cudaFuncSetAttribute(kA, cudaFuncAttributeMaxDynamicSharedMemorySize, A_SMEM);
    cudaFuncSetAttribute(kC, cudaFuncAttributeMaxDynamicSharedMemorySize, C_SMEM);

    kA<<<dim3(100, 4), 256, A_SMEM>>>(c_seq, d_seq, r_seq, X, v_r,
                                      W_ih, b_ih, W2a, b2a);
    kM<<<144, 384>>>(c_seq, d_seq, W_hh, b_hh, v_beta, W2a, W2b, b2b, out);
    kC<<<100, 512, C_SMEM>>>(W1a, b1a, W1b, b1b, out);
}

// round 16
// speedup vs baseline: 1.3716x; 1.3716x over previous
#include <cuda_runtime.h>

#define Bn   32
#define Ln   200
#define Vn   128
#define Gn   384
#define NCn  256
#define NDn  32
#define BTn  (Bn*Ln)          // 6400
#define ASZ  (Bn*Ln*NDn)      // 204800 floats (alpha)
#define HSZ  (Bn*Ln*Vn)       // 819200 floats (h_seq)

// packed-f32x2 helpers (exact fp32 math; halves instruction count)
#define FMA2(acc, a, b) \
    asm("fma.rn.f32x2 %0, %1, %2, %0;" : "+l"(acc) : "l"(a), "l"(b))
#define PACKB(dst, fval) \
    asm("mov.b64 %0, {%1, %1};" : "=l"(dst) : "r"(__float_as_uint(fval)))
__device__ __forceinline__ float2 unpack2(unsigned long long v) {
    unsigned int lo, hi;
    asm("mov.b64 {%0, %1}, %2;" : "=r"(lo), "=r"(hi) : "l"(v));
    return make_float2(__uint_as_float(lo), __uint_as_float(hi));
}

// scratch (module-load allocated, not runtime alloc)
__device__ float g_gx[(size_t)BTn*Gn];     // [bt][384] GRU input projections
__device__ float g_p [(size_t)BTn*Vn];     // [bt][128] memory-path projections
__device__ float g_rows[(size_t)BTn*NDn];  // [bt][32] memory row written at t
__device__ int   g_nextA[BTn];             // next t' with same c (else Ln)
__device__ int   g_firstA[Bn*NCn];         // first t with c (else Ln)
__device__ int   g_done[Bn];               // per-batch beta-chain done flags
__device__ int   g_cnt[100];               // per-m-tile: #finished y<3 kA blocks
__device__ int   g_pf[100];                // per-m-tile: y==3 (g_p) done flag
__device__ int   g_perm[100];              // kA tile processing order

// ============================================================================
// Kernel Z: compute tile priority permutation + reset all flags.
// key(m)=0 if tile [64m,64m+64) contains a batch boundary, else offset within
// its batch. Sort ascending (stable) -> tiles arrive in order of need.
// ============================================================================
__global__ void kZ()
{
    const int t = threadIdx.x;   // 128 threads
    if (t < 100) {
        const int s = 64*t, e = s + 63;
        const int key = (s/200 != e/200 || (s%200) == 0) ? 0 : (s % 200);
        int r = 0;
        for (int m2 = 0; m2 < 100; m2++) {
            const int s2 = 64*m2, e2 = s2 + 63;
            const int k2 = (s2/200 != e2/200 || (s2%200) == 0) ? 0 : (s2 % 200);
            if (k2 < key || (k2 == key && m2 < t)) r++;
        }
        g_perm[r] = t;
        g_cnt[t] = 0;
        g_pf[t]  = 0;
    }
    if (t < Bn) g_done[t] = 0;
}

// ============================================================================
// Monolithic kernel: 560 blocks x 384 threads, dyn smem 103424 B, ~1 block/SM.
//   blocks   0..31 : GRU scan (R14 inner math; waits on g_cnt tile flags)
//   blocks  32..63 : beta chain (R14 inner math; waits on g_pf tile flags)
//   blocks  64..463: kA GEMM tiles (R14 math, 256 of 384 threads; tile order
//                    g_perm; publishes g_cnt / g_pf)
//   blocks 464..559: interval fill of C_seq (waits on g_done)
// ============================================================================
#define A_PAD  68
#define A_WPAD 132
#define A_SMEM ((256*A_PAD + 2*32*A_WPAD)*4)   // 103424

__global__ void __launch_bounds__(384, 1) kMono(
    const int* __restrict__ c_seq, const int* __restrict__ d_seq,
    const float* __restrict__ r_seq, const float* __restrict__ X,
    const float* __restrict__ v_r,
    const float* __restrict__ W_ih, const float* __restrict__ b_ih,
    const float* __restrict__ W_hh, const float* __restrict__ b_hh,
    const float* __restrict__ v_beta, const float* __restrict__ W2a,
    const float* __restrict__ b2a,  const float* __restrict__ W2b,
    const float* __restrict__ b2b,  float* __restrict__ out)
{
    extern __shared__ __align__(16) char smemu[];
    const int blk = blockIdx.x;
    const int tid = threadIdx.x;

    if (blk < 32) {
        // ------------------------- GRU scan -------------------------
        float* h_sh  = (float*)smemu;     // 128 (16B aligned)
        float* s_sh  = h_sh + 128;        // 384
        float* xn_sh = s_sh + 384;        // 128
        const int b = blk;
        const int g = tid;

        unsigned long long w[64];
        {
            const ulonglong2* wr = (const ulonglong2*)(W_hh + (size_t)g*128);
            #pragma unroll
            for (int i = 0; i < 32; i++) {
                ulonglong2 v = wr[i];
                w[2*i] = v.x; w[2*i+1] = v.y;
            }
        }
        const float bh = b_hh[g];
        if (tid < 128) h_sh[tid] = 0.f;
        __syncthreads();

        float* hout = out + ASZ + (size_t)b*Ln*Vn;
        const float* gxp = g_gx + (size_t)b*Ln*Gn;

        int seg_ready = ((b*Ln) >> 6) - 1;
        // wait for segments covering rows t=0,1
        {
            const int segN = (b*Ln + 1) >> 6;
            if (segN > seg_ready) {
                if (tid == 0) {
                    for (int s = seg_ready + 1; s <= segN; s++)
                        while (atomicAdd(&g_cnt[s], 0) < 3) { __nanosleep(100); }
                }
                __syncthreads();
                seg_ready = segN;
            }
        }
        float xg0 = gxp[g];
        float xg1 = gxp[(size_t)Gn + g];

        for (int t = 0; t < Ln; t++) {
            // ensure segment for row t+2 is ready before prefetching it
            {
                const int needT = (t+2 < Ln) ? (t+2) : (Ln-1);
                const int seg = (b*Ln + needT) >> 6;
                if (seg > seg_ready) {
                    if (tid == 0) {
                        for (int s = seg_ready + 1; s <= seg; s++)
                            while (atomicAdd(&g_cnt[s], 0) < 3) { __nanosleep(100); }
                    }
                    __syncthreads();
                    seg_ready = seg;
                }
            }
            float xgN = 0.f;
            if (t+2 < Ln) xgN = gxp[(size_t)(t+2)*Gn + g];

            unsigned long long a0 = 0ull, a1 = 0ull;
            const ulonglong2* h2 = (const ulonglong2*)h_sh;
            #pragma unroll
            for (int kb = 0; kb < 16; kb++) {
                ulonglong2 hA = h2[kb*2+0];
                ulonglong2 hB = h2[kb*2+1];
                FMA2(a0, w[kb*4+0], hA.x); FMA2(a1, w[kb*4+1], hA.y);
                FMA2(a0, w[kb*4+2], hB.x); FMA2(a1, w[kb*4+3], hB.y);
            }
            float2 f0 = unpack2(a0), f1 = unpack2(a1);
            const float gh = (f0.x + f0.y) + (f1.x + f1.y) + bh;
            if (g < 256) s_sh[g] = xg0 + gh;
            else { s_sh[g] = gh; xn_sh[g-256] = xg0; }
            xg0 = xg1; xg1 = xgN;
            __syncthreads();
            if (tid < 128) {
                const int j = tid;
                float sr = s_sh[j], sz = s_sh[j+128], sn = s_sh[j+256];
                float r = __fdividef(1.f, 1.f + __expf(-sr));
                float z = __fdividef(1.f, 1.f + __expf(-sz));
                float np = xn_sh[j] + r*sn;
                float e  = __expf(-2.f*np);
                float nn = __fdividef(1.f - e, 1.f + e);
                float h  = h_sh[j];
                h = (1.f - z)*nn + z*h;
                h_sh[j] = h;
                hout[(size_t)t*Vn + j] = h;
            }
            __syncthreads();
        }

    } else if (blk < 64) {
        // ---------------- beta chain (per batch) ----------------
        float* C_sh   = (float*)smemu;            // 8192 floats (32 KB)
        float* u_sh   = C_sh + NCn*NDn;           // 128
        float* pre_sh = u_sh + 128;               // 128
        const int b = blk - 32;

        for (int i = tid; i < NCn*NDn; i += 384) C_sh[i] = 0.f;
        if (tid < 128) {
            float acc = 0.f;
            const float* wr = W2a + (size_t)tid*384;
            #pragma unroll 8
            for (int j = 0; j < 128; j++) acc += v_beta[j]*wr[j];
            u_sh[tid] = acc;
        }

        float4 wb0={0,0,0,0}, wb1={0,0,0,0}, wb2={0,0,0,0}, wb3={0,0,0,0};
        float bb = 0.f;
        int dd = 0, s = 0;
        if (tid < 256) {
            dd = tid >> 3; s = tid & 7;
            const float4* wr = (const float4*)(W2b + (size_t)dd*128 + s*16);
            wb0 = wr[0]; wb1 = wr[1]; wb2 = wr[2]; wb3 = wr[3];
            bb = b2b[dd];
        }
        __syncthreads();

        const float* pp = g_p + (size_t)b*Ln*Vn;
        const int* cs = c_seq + b*Ln;
        const int* ds = d_seq + b*Ln;

        int seg_ready = ((b*Ln) >> 6) - 1;
        {
            const int segN = (b*Ln + 1) >> 6;
            if (segN > seg_ready) {
                if (tid == 0) {
                    for (int ss = seg_ready + 1; ss <= segN; ss++)
                        while (atomicAdd(&g_pf[ss], 0) == 0) { __nanosleep(100); }
                }
                __syncthreads();
                seg_ready = segN;
            }
        }

        int ct = cs[0], dt = ds[0];
        float pv0 = 0.f, pv1 = 0.f;
        if (tid < 128) { pv0 = pp[tid]; pv1 = pp[Vn + tid]; }

        for (int t = 0; t < Ln; t++) {
            {
                const int needT = (t+2 < Ln) ? (t+2) : (Ln-1);
                const int seg = (b*Ln + needT) >> 6;
                if (seg > seg_ready) {
                    if (tid == 0) {
                        for (int ss = seg_ready + 1; ss <= seg; ss++)
                            while (atomicAdd(&g_pf[ss], 0) == 0) { __nanosleep(100); }
                    }
                    __syncthreads();
                    seg_ready = seg;
                }
            }
            float pvN = 0.f;
            if (t+2 < Ln && tid < 128) pvN = pp[(size_t)(t+2)*Vn + tid];
            int ctn = ct, dtn = dt;
            if (t+1 < Ln) { ctn = cs[t+1]; dtn = ds[t+1]; }

            const float beta = C_sh[ct*NDn + dt];
            if (tid < 128) pre_sh[tid] = fmaxf(beta*u_sh[tid] + pv0, 0.f);
            __syncthreads();
            if (tid < 256) {
                const float4* pr = (const float4*)&pre_sh[s*16];
                float4 p0 = pr[0], p1 = pr[1], p2 = pr[2], p3 = pr[3];
                float acc = wb0.x*p0.x + wb0.y*p0.y + wb0.z*p0.z + wb0.w*p0.w
                          + wb1.x*p1.x + wb1.y*p1.y + wb1.z*p1.z + wb1.w*p1.w
                          + wb2.x*p2.x + wb2.y*p2.y + wb2.z*p2.z + wb2.w*p2.w
                          + wb3.x*p3.x + wb3.y*p3.y + wb3.z*p3.z + wb3.w*p3.w;
                acc += __shfl_down_sync(0xffffffffu, acc, 4, 8);
                acc += __shfl_down_sync(0xffffffffu, acc, 2, 8);
                acc += __shfl_down_sync(0xffffffffu, acc, 1, 8);
                if (s == 0) {
                    const float v = acc + bb;
                    C_sh[ct*NDn + dd] = v;
                    g_rows[((size_t)b*Ln + t)*NDn + dd] = v;
                }
            }
            __syncthreads();
            ct = ctn; dt = dtn; pv0 = pv1; pv1 = pvN;
        }

        // ---- index epilogue ----
        __syncthreads();
        int* csm = (int*)smemu;
        for (int i = tid; i < Ln; i += 384) csm[i] = cs[i];
        __syncthreads();
        if (tid < Ln) {
            const int c = csm[tid];
            int nt = Ln;
            for (int tt = tid+1; tt < Ln; tt++) if (csm[tt] == c) { nt = tt; break; }
            g_nextA[b*Ln + tid] = nt;
        } else if (tid < Ln + NCn) {
            const int c = tid - Ln;
            int ft = Ln;
            for (int tt = 0; tt < Ln; tt++) if (csm[tt] == c) { ft = tt; break; }
            g_firstA[b*NCn + c] = ft;
        }
        __threadfence();
        __syncthreads();
        if (tid == 0) atomicExch(&g_done[b], 1);

    } else if (blk < 464) {
        // ----------------------- kA GEMM tile -----------------------
        float* sm  = (float*)smemu;
        float* inT = sm;                      // [k 256][m 68-pad]
        float* Wt0 = sm + 256*A_PAD;          // two [k 32][n 132-pad]
        const int ka  = blk - 64;             // 0..399
        const int mt  = g_perm[ka >> 2];      // priority-ordered m tile
        const int y   = ka & 3;
        const int bt0 = mt * 64;
        const int n0  = y * 128;
        const int lane = tid & 31;
        const int warp = tid >> 5;

        if (tid < 256) {
            const int m = tid & 63;
            const int q = tid >> 6;          // 0..3
            const int bt = bt0 + m;
            const int c  = c_seq[bt];
            const int d  = d_seq[bt];
            const float r = r_seq[bt];
            if (q < 2) {
                const float4* src = (const float4*)(X + (size_t)(c + NCn*d)*Vn + q*64);
                #pragma unroll
                for (int u = 0; u < 16; u++) {
                    float4 v = src[u];
                    int k = q*64 + u*4;
                    inT[(k+0)*A_PAD+m] = v.x; inT[(k+1)*A_PAD+m] = v.y;
                    inT[(k+2)*A_PAD+m] = v.z; inT[(k+3)*A_PAD+m] = v.w;
                }
            } else {
                const int kb = (q - 2) * 64;
                const float4* src = (const float4*)(v_r + kb);
                #pragma unroll
                for (int u = 0; u < 16; u++) {
                    float4 v = src[u];
                    int k = 128 + kb + u*4;
                    inT[(k+0)*A_PAD+m] = r*v.x; inT[(k+1)*A_PAD+m] = r*v.y;
                    inT[(k+2)*A_PAD+m] = r*v.z; inT[(k+3)*A_PAD+m] = r*v.w;
                }
            }
        }

        const int nl  = tid & 127;
        const int kq2 = (tid >> 7) & 1;       // 0..1 for tid<256
        const int n   = n0 + nl;
        const float4* wsrc = (const float4*)((n < Gn)
                           ? (W_ih + (size_t)n*256)
                           : (W2a + (size_t)(n - Gn)*384 + 128));

        float4 wr0, wr1, wr2, wr3;
        if (tid < 256) {
            wr0 = wsrc[kq2*4+0]; wr1 = wsrc[kq2*4+1];
            wr2 = wsrc[kq2*4+2]; wr3 = wsrc[kq2*4+3];
        }

        const int mq = warp * 8;              // 0..56 for warps 0..7
        const int nq = lane * 4;              // 0..124

        unsigned long long acc[16];
        #pragma unroll
        for (int i = 0; i < 16; i++) acc[i] = 0ull;

        for (int kb = 0; kb < 8; kb++) {
            float* Wt = Wt0 + (kb & 1) * (32*A_WPAD);
            if (tid < 256) {
                int k = kq2*16;
                Wt[(k+ 0)*A_WPAD+nl]=wr0.x; Wt[(k+ 1)*A_WPAD+nl]=wr0.y; Wt[(k+ 2)*A_WPAD+nl]=wr0.z; Wt[(k+ 3)*A_WPAD+nl]=wr0.w;
                Wt[(k+ 4)*A_WPAD+nl]=wr1.x; Wt[(k+ 5)*A_WPAD+nl]=wr1.y; Wt[(k+ 6)*A_WPAD+nl]=wr1.z; Wt[(k+ 7)*A_WPAD+nl]=wr1.w;
                Wt[(k+ 8)*A_WPAD+nl]=wr2.x; Wt[(k+ 9)*A_WPAD+nl]=wr2.y; Wt[(k+10)*A_WPAD+nl]=wr2.z; Wt[(k+11)*A_WPAD+nl]=wr2.w;
                Wt[(k+12)*A_WPAD+nl]=wr3.x; Wt[(k+13)*A_WPAD+nl]=wr3.y; Wt[(k+14)*A_WPAD+nl]=wr3.z; Wt[(k+15)*A_WPAD+nl]=wr3.w;
                if (kb < 7) {
                    wr0 = wsrc[(kb+1)*8 + kq2*4 + 0];
                    wr1 = wsrc[(kb+1)*8 + kq2*4 + 1];
                    wr2 = wsrc[(kb+1)*8 + kq2*4 + 2];
                    wr3 = wsrc[(kb+1)*8 + kq2*4 + 3];
                }
            }
            __syncthreads();
            if (tid < 256) {
                const float* inb = inT + (kb*32)*A_PAD + mq;
                const float* wb  = Wt + nq;
                #pragma unroll
                for (int kk = 0; kk < 32; kk++) {
                    float4 aA = *(const float4*)(inb + kk*A_PAD);
                    float4 aB = *(const float4*)(inb + kk*A_PAD + 4);
                    ulonglong2 wv = *(const ulonglong2*)(wb + kk*A_WPAD);
                    unsigned long long p;
                    PACKB(p, aA.x); FMA2(acc[ 0], p, wv.x); FMA2(acc[ 1], p, wv.y);
                    PACKB(p, aA.y); FMA2(acc[ 2], p, wv.x); FMA2(acc[ 3], p, wv.y);
                    PACKB(p, aA.z); FMA2(acc[ 4], p, wv.x); FMA2(acc[ 5], p, wv.y);
                    PACKB(p, aA.w); FMA2(acc[ 6], p, wv.x); FMA2(acc[ 7], p, wv.y);
                    PACKB(p, aB.x); FMA2(acc[ 8], p, wv.x); FMA2(acc[ 9], p, wv.y);
                    PACKB(p, aB.y); FMA2(acc[10], p, wv.x); FMA2(acc[11], p, wv.y);
                    PACKB(p, aB.z); FMA2(acc[12], p, wv.x); FMA2(acc[13], p, wv.y);
                    PACKB(p, aB.w); FMA2(acc[14], p, wv.x); FMA2(acc[15], p, wv.y);
                }
            }
        }

        if (tid < 256) {
            const int nn = n0 + nq;
            if (n0 < Gn) {
                float b0=b_ih[nn], b1=b_ih[nn+1], b2=b_ih[nn+2], b3=b_ih[nn+3];
                #pragma unroll
                for (int i = 0; i < 8; i++) {
                    float2 lo = unpack2(acc[2*i]), hi = unpack2(acc[2*i+1]);
                    *(float4*)(g_gx + (size_t)(bt0+mq+i)*Gn + nn) =
                        make_float4(lo.x+b0, lo.y+b1, hi.x+b2, hi.y+b3);
                }
            } else {
                const int pc = nn - Gn;
                float b0=b2a[pc], b1=b2a[pc+1], b2=b2a[pc+2], b3=b2a[pc+3];
                #pragma unroll
                for (int i = 0; i < 8; i++) {
                    float2 lo = unpack2(acc[2*i]), hi = unpack2(acc[2*i+1]);
                    *(float4*)(g_p + (size_t)(bt0+mq+i)*Vn + pc) =
                        make_float4(lo.x+b0, lo.y+b1, hi.x+b2, hi.y+b3);
                }
            }
        }
        // publish tile completion
        __threadfence();
        __syncthreads();
        if (tid == 0) {
            if (y < 3) atomicAdd(&g_cnt[mt], 1);
            else       atomicExch(&g_pf[mt], 1);
        }

    } else {
        // -------------------- interval fill of C_seq --------------------
        const int fb  = blk - 464;        // 0..95
        const int b   = fb / 3;
        const int sub = fb % 3;
        if (tid == 0) {
            while (atomicAdd(&g_done[b], 0) == 0) { __nanosleep(200); }
        }
        __syncthreads();

        const int wid = tid >> 5, lane = tid & 31;
        float* Cout = out + ASZ + HSZ + (size_t)b*Ln*NCn*NDn;
        const int* cs = c_seq + b*Ln;

        for (int task = sub*12 + wid; task < Ln + NCn; task += 36) {
            if (task < Ln) {
                const int t  = task;
                const int c  = cs[t];
                const int te = g_nextA[b*Ln + t];
                const float val = g_rows[((size_t)b*Ln + t)*NDn + lane];
                float* dst = Cout + (size_t)t*(NCn*NDn) + c*NDn + lane;
                for (int tp = t; tp < te; tp++) {
                    __stcs(dst, val);
                    dst += NCn*NDn;
                }
            } else {
                const int c  = task - Ln;
                const int te = g_firstA[b*NCn + c];
                float* dst = Cout + c*NDn + lane;
                for (int tp = 0; tp < te; tp++) {
                    __stcs(dst, 0.f);
                    dst += NCn*NDn;
                }
            }
        }
    }
}

// ============================================================================
// Kernel C: alpha = relu(h@W1a^T + b1a)@W1b^T + b1b   (M=6400)  [R14 verbatim]
// ============================================================================
#define C_SMEM ((128*68 + 128*132 + 128*36 + 64*136)*4)   // 155648 B

__global__ void __launch_bounds__(512, 1) kC(
    const float* __restrict__ W1a, const float* __restrict__ b1a,
    const float* __restrict__ W1b, const float* __restrict__ b1b,
    float* __restrict__ out)
{
    extern __shared__ float sm[];
    float* hT   = sm;                       // [j 128][m 68-pad]
    float* WaT  = hT  + 128*68;             // [j 128][i 132-pad]
    float* WbT  = WaT + 128*132;            // [i 128][dd 36-pad]
    float* hid  = WbT + 128*36;             // [m 64][i 136-pad]
    const int tid = threadIdx.x;
    const int bt0 = blockIdx.x * 64;
    const float* hseq = out + ASZ;

    {
        const int m = tid & 63;
        const int jq = tid >> 6;    // 0..7
        const float4* src = (const float4*)(hseq + (size_t)(bt0+m)*Vn + jq*16);
        #pragma unroll
        for (int u = 0; u < 4; u++) {
            float4 v = src[u];
            int j = jq*16 + u*4;
            hT[(j+0)*68+m]=v.x; hT[(j+1)*68+m]=v.y; hT[(j+2)*68+m]=v.z; hT[(j+3)*68+m]=v.w;
        }
    }
    {
        const int i = tid & 127;
        const int jq = tid >> 7;    // 0..3
        const float4* src = (const float4*)(W1a + (size_t)i*128 + jq*32);
        #pragma unroll
        for (int u = 0; u < 8; u++) {
            float4 v = src[u];
            int j = jq*32 + u*4;
            WaT[(j+0)*132+i]=v.x; WaT[(j+1)*132+i]=v.y; WaT[(j+2)*132+i]=v.z; WaT[(j+3)*132+i]=v.w;
        }
    }
    if (tid < 256) {
        const int dd = tid & 31;
        const int iq = tid >> 5;    // 0..7
        const float4* src = (const float4*)(W1b + (size_t)dd*128 + iq*16);
        #pragma unroll
        for (int u = 0; u < 4; u++) {
            float4 v = src[u];
            int i = iq*16 + u*4;
            WbT[(i+0)*36+dd]=v.x; WbT[(i+1)*36+dd]=v.y; WbT[(i+2)*36+dd]=v.z; WbT[(i+3)*36+dd]=v.w;
        }
    }
    __syncthreads();

    {
        const int mq = (tid >> 5) * 4;      // 0..60
        const int iq = (tid & 31) * 4;      // 0..124
        unsigned long long acc[8];
        #pragma unroll
        for (int i = 0; i < 8; i++) acc[i] = 0ull;
        #pragma unroll 8
        for (int j = 0; j < 128; j++) {
            float4 h4 = *(const float4*)&hT[j*68 + mq];           // broadcast
            ulonglong2 wv = *(const ulonglong2*)&WaT[j*132 + iq];
            unsigned long long p;
            PACKB(p, h4.x); FMA2(acc[0], p, wv.x); FMA2(acc[1], p, wv.y);
            PACKB(p, h4.y); FMA2(acc[2], p, wv.x); FMA2(acc[3], p, wv.y);
            PACKB(p, h4.z); FMA2(acc[4], p, wv.x); FMA2(acc[5], p, wv.y);
            PACKB(p, h4.w); FMA2(acc[6], p, wv.x); FMA2(acc[7], p, wv.y);
        }
        float2 u0 = unpack2(acc[0]), u1 = unpack2(acc[1]);
        float2 u2 = unpack2(acc[2]), u3 = unpack2(acc[3]);
        float2 u4 = unpack2(acc[4]), u5 = unpack2(acc[5]);
        float2 u6 = unpack2(acc[6]), u7 = unpack2(acc[7]);
        float b0=b1a[iq], b1=b1a[iq+1], b2=b1a[iq+2], b3=b1a[iq+3];
        *(float4*)&hid[(mq+0)*136 + iq] = make_float4(fmaxf(u0.x+b0,0.f), fmaxf(u0.y+b1,0.f), fmaxf(u1.x+b2,0.f), fmaxf(u1.y+b3,0.f));
        *(float4*)&hid[(mq+1)*136 + iq] = make_float4(fmaxf(u2.x+b0,0.f), fmaxf(u2.y+b1,0.f), fmaxf(u3.x+b2,0.f), fmaxf(u3.y+b3,0.f));
        *(float4*)&hid[(mq+2)*136 + iq] = make_float4(fmaxf(u4.x+b0,0.f), fmaxf(u4.y+b1,0.f), fmaxf(u5.x+b2,0.f), fmaxf(u5.y+b3,0.f));
        *(float4*)&hid[(mq+3)*136 + iq] = make_float4(fmaxf(u6.x+b0,0.f), fmaxf(u6.y+b1,0.f), fmaxf(u7.x+b2,0.f), fmaxf(u7.y+b3,0.f));
    }
    __syncthreads();

    {
        const int m2 = tid & 63;            // 0..63
        const int d4 = (tid >> 6) * 4;      // 0..28
        float c0=0.f, c1=0.f, c2=0.f, c3=0.f;
        const float* hrow = hid + m2*136;
        #pragma unroll 8
        for (int i4 = 0; i4 < 32; i4++) {
            float4 hq = *(const float4*)(hrow + i4*4);
            float4 wA = *(const float4*)&WbT[(i4*4+0)*36 + d4];
            float4 wB = *(const float4*)&WbT[(i4*4+1)*36 + d4];
            float4 wC = *(const float4*)&WbT[(i4*4+2)*36 + d4];
            float4 wD = *(const float4*)&WbT[(i4*4+3)*36 + d4];
            c0 += hq.x*wA.x + hq.y*wB.x + hq.z*wC.x + hq.w*wD.x;
            c1 += hq.x*wA.y + hq.y*wB.y + hq.z*wC.y + hq.w*wD.y;
            c2 += hq.x*wA.z + hq.y*wB.z + hq.z*wC.z + hq.w*wD.z;
            c3 += hq.x*wA.w + hq.y*wB.w + hq.z*wC.w + hq.w*wD.w;
        }
        float4 ov = make_float4(c0 + b1b[d4], c1 + b1b[d4+1], c2 + b1b[d4+2], c3 + b1b[d4+3]);
        *(float4*)&out[(size_t)(bt0+m2)*NDn + d4] = ov;
    }
}

// ============================================================================
extern "C" void kernel_launch(void* const* d_in, const int* in_sizes, int n_in,
                              void* d_out, int out_size)
{
    const int*   c_seq  = (const int*)  d_in[0];
    const int*   d_seq  = (const int*)  d_in[1];
    const float* r_seq  = (const float*)d_in[2];
    const float* X      = (const float*)d_in[3];
    const float* v_r    = (const float*)d_in[4];
    const float* v_beta = (const float*)d_in[5];
    const float* W_ih   = (const float*)d_in[6];
    const float* W_hh   = (const float*)d_in[7];
    const float* b_ih   = (const float*)d_in[8];
    const float* b_hh   = (const float*)d_in[9];
    const float* W1a    = (const float*)d_in[10];
    const float* b1a    = (const float*)d_in[11];
    const float* W1b    = (const float*)d_in[12];
    const float* b1b    = (const float*)d_in[13];
    const float* W2a    = (const float*)d_in[14];
    const float* b2a    = (const float*)d_in[15];
    const float* W2b    = (const float*)d_in[16];
    const float* b2b    = (const float*)d_in[17];
    float* out = (float*)d_out;

    cudaFuncSetAttribute(kMono, cudaFuncAttributeMaxDynamicSharedMemorySize, A_SMEM);
    cudaFuncSetAttribute(kC,    cudaFuncAttributeMaxDynamicSharedMemorySize, C_SMEM);

    kZ<<<1, 128>>>();
    kMono<<<560, 384, A_SMEM>>>(c_seq, d_seq, r_seq, X, v_r,
                                W_ih, b_ih, W_hh, b_hh, v_beta,
                                W2a, b2a, W2b, b2b, out);
    kC<<<100, 512, C_SMEM>>>(W1a, b1a, W1b, b1b, out);
}